// round 2
// baseline (speedup 1.0000x reference)
#include <cuda_runtime.h>
#include <math.h>

#define N_NODES 4096
#define C 256
#define NH 4
#define CH 64
#define ALPHA 0.2f

// ---------------- device scratch (no allocs allowed) ----------------
__device__ float g_feats[N_NODES * C];          // 4 MB
__device__ float g_src[N_NODES * NH];
__device__ float g_dst[N_NODES * NH];
__device__ float g_E1[N_NODES * NH];            // exp(dst)
__device__ float g_E2[N_NODES * NH];            // exp(alpha*dst)
__device__ unsigned int g_maxdst_enc[NH];       // monotone-encoded float max

// monotone encoding of float for atomicMax on unsigned
__device__ __forceinline__ unsigned int fenc(float f) {
    unsigned int u = __float_as_uint(f);
    return (u & 0x80000000u) ? ~u : (u | 0x80000000u);
}
__device__ __forceinline__ float fdec(unsigned int u) {
    return (u & 0x80000000u) ? __uint_as_float(u ^ 0x80000000u)
                             : __uint_as_float(~u);
}

// ---------------- init ----------------
__global__ void init_kernel() {
    if (threadIdx.x < NH) g_maxdst_enc[threadIdx.x] = 0u;  // below enc(-inf)
}

// ---------------- phase 1: feats = X @ W + b ----------------
// X [4096,256], W [256,256], tiles 64x64, BK=16, 256 threads, 4x4 microtile
__global__ __launch_bounds__(256) void gemm_feats(
    const float* __restrict__ X, const float* __restrict__ W,
    const float* __restrict__ bias)
{
    __shared__ float As[16][64];
    __shared__ float Bs[16][64];

    const int tid = threadIdx.x;
    const int tx = tid & 15;
    const int ty = tid >> 4;
    const int bm = blockIdx.y * 64;
    const int bn = blockIdx.x * 64;

    float acc[4][4] = {};

    for (int k0 = 0; k0 < C; k0 += 16) {
        // load A tile (64 rows x 16 k), transposed store
        {
            int row = tid >> 2;            // 0..63
            int kc  = (tid & 3) * 4;       // 0,4,8,12
            float4 v = *(const float4*)&X[(size_t)(bm + row) * C + k0 + kc];
            As[kc + 0][row] = v.x;
            As[kc + 1][row] = v.y;
            As[kc + 2][row] = v.z;
            As[kc + 3][row] = v.w;
        }
        // load B tile (16 k x 64 cols)
        {
            int kr = tid >> 4;             // 0..15
            int cc = (tid & 15) * 4;       // 0..60
            *(float4*)&Bs[kr][cc] =
                *(const float4*)&W[(size_t)(k0 + kr) * C + bn + cc];
        }
        __syncthreads();

#pragma unroll
        for (int kk = 0; kk < 16; kk++) {
            float4 a4 = *(const float4*)&As[kk][ty * 4];
            float4 b4 = *(const float4*)&Bs[kk][tx * 4];
            float av[4] = {a4.x, a4.y, a4.z, a4.w};
            float bv[4] = {b4.x, b4.y, b4.z, b4.w};
#pragma unroll
            for (int i = 0; i < 4; i++)
#pragma unroll
                for (int j = 0; j < 4; j++)
                    acc[i][j] += av[i] * bv[j];
        }
        __syncthreads();
    }

#pragma unroll
    for (int i = 0; i < 4; i++) {
#pragma unroll
        for (int j = 0; j < 4; j++) {
            int r = bm + ty * 4 + i;
            int c = bn + tx * 4 + j;
            g_feats[(size_t)r * C + c] = acc[i][j] + bias[c];
        }
    }
}

// ---------------- phase 2: src/dst + exp factors + maxdst ----------------
// one warp per node; a is [NH][2*CH] = [4][128]
__global__ __launch_bounds__(256) void srcdst_kernel(const float* __restrict__ a)
{
    const int warp = threadIdx.x >> 5;
    const int lane = threadIdx.x & 31;
    const int n = blockIdx.x * 8 + warp;
    if (n >= N_NODES) return;

    const float* f = g_feats + (size_t)n * C;

#pragma unroll
    for (int h = 0; h < NH; h++) {
        float f0 = f[h * 64 + lane];
        float f1 = f[h * 64 + 32 + lane];
        float as0 = a[h * 128 + lane];
        float as1 = a[h * 128 + 32 + lane];
        float ad0 = a[h * 128 + 64 + lane];
        float ad1 = a[h * 128 + 96 + lane];
        float vs = f0 * as0 + f1 * as1;
        float vd = f0 * ad0 + f1 * ad1;
#pragma unroll
        for (int o = 16; o; o >>= 1) {
            vs += __shfl_xor_sync(0xFFFFFFFFu, vs, o);
            vd += __shfl_xor_sync(0xFFFFFFFFu, vd, o);
        }
        if (lane == 0) {
            g_src[n * NH + h] = vs;
            g_dst[n * NH + h] = vd;
            g_E1[n * NH + h] = expf(vd);
            g_E2[n * NH + h] = expf(ALPHA * vd);
            atomicMax(&g_maxdst_enc[h], fenc(vd));
        }
    }
}

// ---------------- phase 3: masked-softmax attention + PV (fused) ----------------
// grid (NH, N/32); block 256 threads; head fastest for adj L2 reuse.
// Thread t: column cg = t&63 of its head, i-range = (t>>6)*8 .. +8 (packed f32x2).
__global__ __launch_bounds__(256) void attn_kernel(
    const int* __restrict__ adj, float* __restrict__ out)
{
    __shared__ float s_src[32], s_P1[32], s_P2[32];
    __shared__ float s_prob[32][36];   // [j][i], pad 36 -> conflict-lite STS, 16B-aligned rows
    __shared__ float s_feat[32][64];   // [j][cg]
    __shared__ float s_sum[32];

    const int h  = blockIdx.x;
    const int i0 = blockIdx.y * 32;
    const int tid = threadIdx.x;
    const int cg = tid & 63;           // column within head
    const int ig = tid >> 6;           // 0..3 -> i block of 8
    const int jj = tid & 31;           // j lane for prob compute
    const int wp = tid >> 5;           // warp id 0..7 -> i4

    if (tid < 32) {
        float src = g_src[(i0 + tid) * NH + h];
        float md = fdec(g_maxdst_enc[h]);
        float bb = src + md;
        bb = (bb >= 0.f) ? bb : ALPHA * bb;     // b_i = leaky(src + max_dst) >= all logits
        s_src[tid] = src;
        s_P1[tid] = expf(src - bb);
        s_P2[tid] = expf(ALPHA * src - bb);
    }
    __syncthreads();

    unsigned long long acc[4] = {0ull, 0ull, 0ull, 0ull};  // 8 fp32 accumulators, packed
    float psum[4] = {0.f, 0.f, 0.f, 0.f};

    const float* fbase = g_feats + h * 64 + cg;

    for (int jc = 0; jc < N_NODES / 32; jc++) {
        const int j0 = jc * 32;

        // ---- stage feats chunk [32][64] ----
#pragma unroll
        for (int r = 0; r < 8; r++) {
            int j = r * 4 + ig;
            s_feat[j][cg] = fbase[(size_t)(j0 + j) * C];
        }

        // ---- compute probs [32j][32i] for this head ----
        {
            int g = (j0 + jj) * NH + h;
            float d  = g_dst[g];
            float e1 = g_E1[g];
            float e2 = g_E2[g];
#pragma unroll
            for (int ii = 0; ii < 4; ii++) {
                int i = wp + 8 * ii;
                int av = adj[(size_t)(i0 + i) * N_NODES + j0 + jj];
                float s = s_src[i] + d;
                float p = (av == 1)
                            ? ((s >= 0.f) ? s_P1[i] * e1 : s_P2[i] * e2)
                            : 0.f;
                s_prob[jj][i] = p;
                psum[ii] += p;
            }
        }
        __syncthreads();

        // ---- PV accumulate: packed fp32 FMA (fma.rn.f32x2) ----
#pragma unroll 8
        for (int j = 0; j < 32; j++) {
            float fv = s_feat[j][cg];
            unsigned long long ff;
            asm("mov.b64 %0, {%1, %1};" : "=l"(ff) : "f"(fv));
            const unsigned long long* pr =
                (const unsigned long long*)&s_prob[j][ig * 8];
            unsigned long long p0 = pr[0], p1 = pr[1], p2 = pr[2], p3 = pr[3];
            asm("fma.rn.f32x2 %0, %1, %2, %0;" : "+l"(acc[0]) : "l"(p0), "l"(ff));
            asm("fma.rn.f32x2 %0, %1, %2, %0;" : "+l"(acc[1]) : "l"(p1), "l"(ff));
            asm("fma.rn.f32x2 %0, %1, %2, %0;" : "+l"(acc[2]) : "l"(p2), "l"(ff));
            asm("fma.rn.f32x2 %0, %1, %2, %0;" : "+l"(acc[3]) : "l"(p3), "l"(ff));
        }
        __syncthreads();
    }

    // ---- reduce denominators: warp wp holds i = wp + 8*ii across jj lanes ----
#pragma unroll
    for (int ii = 0; ii < 4; ii++) {
        float v = psum[ii];
#pragma unroll
        for (int o = 16; o; o >>= 1) v += __shfl_xor_sync(0xFFFFFFFFu, v, o);
        if (jj == 0) s_sum[wp + 8 * ii] = v;
    }
    __syncthreads();

    // ---- write normalized output ----
#pragma unroll
    for (int k = 0; k < 4; k++) {
        float lo, hi;
        asm("mov.b64 {%0, %1}, %2;" : "=f"(lo), "=f"(hi) : "l"(acc[k]));
        int iA = ig * 8 + 2 * k;
        int iB = iA + 1;
        out[(size_t)(i0 + iA) * C + h * 64 + cg] = lo / s_sum[iA];
        out[(size_t)(i0 + iB) * C + h * 64 + cg] = hi / s_sum[iB];
    }
}

// ---------------- launch ----------------
extern "C" void kernel_launch(void* const* d_in, const int* in_sizes, int n_in,
                              void* d_out, int out_size)
{
    const float* node_feats = (const float*)d_in[0];
    const int*   adj        = (const int*)d_in[1];
    const float* W          = (const float*)d_in[2];
    const float* b          = (const float*)d_in[3];
    const float* a          = (const float*)d_in[4];
    float* out = (float*)d_out;

    init_kernel<<<1, 32>>>();
    gemm_feats<<<dim3(C / 64, N_NODES / 64), 256>>>(node_feats, W, b);
    srcdst_kernel<<<N_NODES / 8, 256>>>(a);
    attn_kernel<<<dim3(NH, N_NODES / 32), 256>>>(adj, out);
}

// round 3
// speedup vs baseline: 1.0255x; 1.0255x over previous
#include <cuda_runtime.h>
#include <math.h>

#define N_NODES 4096
#define C 256
#define NH 4
#define CH 64
#define ALPHA 0.2f

// ---------------- device scratch (no allocs allowed) ----------------
__device__ float g_feats[N_NODES * C];          // 4 MB
__device__ float g_src[N_NODES * NH];
__device__ float g_dst[N_NODES * NH];
__device__ float g_E1[N_NODES * NH];            // exp(dst)
__device__ float g_E2[N_NODES * NH];            // exp(alpha*dst)
__device__ unsigned int g_maxdst_enc[NH];       // monotone-encoded float max

// monotone encoding of float for atomicMax on unsigned
__device__ __forceinline__ unsigned int fenc(float f) {
    unsigned int u = __float_as_uint(f);
    return (u & 0x80000000u) ? ~u : (u | 0x80000000u);
}
__device__ __forceinline__ float fdec(unsigned int u) {
    return (u & 0x80000000u) ? __uint_as_float(u ^ 0x80000000u)
                             : __uint_as_float(~u);
}

// ---------------- init ----------------
__global__ void init_kernel() {
    if (threadIdx.x < NH) g_maxdst_enc[threadIdx.x] = 0u;  // below enc(-inf)
}

// ---------------- phase 1: feats = X @ W + b ----------------
// X [4096,256], W [256,256], tiles 64x64, BK=16, 256 threads, 4x4 microtile
__global__ __launch_bounds__(256) void gemm_feats(
    const float* __restrict__ X, const float* __restrict__ W,
    const float* __restrict__ bias)
{
    __shared__ float As[16][64];
    __shared__ float Bs[16][64];

    const int tid = threadIdx.x;
    const int tx = tid & 15;
    const int ty = tid >> 4;
    const int bm = blockIdx.y * 64;
    const int bn = blockIdx.x * 64;

    float acc[4][4] = {};

    for (int k0 = 0; k0 < C; k0 += 16) {
        // load A tile (64 rows x 16 k), transposed store
        {
            int row = tid >> 2;            // 0..63
            int kc  = (tid & 3) * 4;       // 0,4,8,12
            float4 v = *(const float4*)&X[(size_t)(bm + row) * C + k0 + kc];
            As[kc + 0][row] = v.x;
            As[kc + 1][row] = v.y;
            As[kc + 2][row] = v.z;
            As[kc + 3][row] = v.w;
        }
        // load B tile (16 k x 64 cols)
        {
            int kr = tid >> 4;             // 0..15
            int cc = (tid & 15) * 4;       // 0..60
            *(float4*)&Bs[kr][cc] =
                *(const float4*)&W[(size_t)(k0 + kr) * C + bn + cc];
        }
        __syncthreads();

#pragma unroll
        for (int kk = 0; kk < 16; kk++) {
            float4 a4 = *(const float4*)&As[kk][ty * 4];
            float4 b4 = *(const float4*)&Bs[kk][tx * 4];
            float av[4] = {a4.x, a4.y, a4.z, a4.w};
            float bv[4] = {b4.x, b4.y, b4.z, b4.w};
#pragma unroll
            for (int i = 0; i < 4; i++)
#pragma unroll
                for (int j = 0; j < 4; j++)
                    acc[i][j] += av[i] * bv[j];
        }
        __syncthreads();
    }

#pragma unroll
    for (int i = 0; i < 4; i++) {
#pragma unroll
        for (int j = 0; j < 4; j++) {
            int r = bm + ty * 4 + i;
            int c = bn + tx * 4 + j;
            g_feats[(size_t)r * C + c] = acc[i][j] + bias[c];
        }
    }
}

// ---------------- phase 2: src/dst + exp factors + maxdst ----------------
// one warp per node; a is [NH][2*CH] = [4][128]
__global__ __launch_bounds__(256) void srcdst_kernel(const float* __restrict__ a)
{
    const int warp = threadIdx.x >> 5;
    const int lane = threadIdx.x & 31;
    const int n = blockIdx.x * 8 + warp;
    if (n >= N_NODES) return;

    const float* f = g_feats + (size_t)n * C;

#pragma unroll
    for (int h = 0; h < NH; h++) {
        float f0 = f[h * 64 + lane];
        float f1 = f[h * 64 + 32 + lane];
        float as0 = a[h * 128 + lane];
        float as1 = a[h * 128 + 32 + lane];
        float ad0 = a[h * 128 + 64 + lane];
        float ad1 = a[h * 128 + 96 + lane];
        float vs = f0 * as0 + f1 * as1;
        float vd = f0 * ad0 + f1 * ad1;
#pragma unroll
        for (int o = 16; o; o >>= 1) {
            vs += __shfl_xor_sync(0xFFFFFFFFu, vs, o);
            vd += __shfl_xor_sync(0xFFFFFFFFu, vd, o);
        }
        if (lane == 0) {
            g_src[n * NH + h] = vs;
            g_dst[n * NH + h] = vd;
            g_E1[n * NH + h] = expf(vd);
            g_E2[n * NH + h] = expf(ALPHA * vd);
            atomicMax(&g_maxdst_enc[h], fenc(vd));
        }
    }
}

// ---------------- phase 3: masked-softmax attention + PV (fused) ----------------
// grid (NH, N/32); block 256 threads; head fastest for adj L2 reuse.
// Thread t: column cg = t&63 of its head, i-range = (t>>6)*8 .. +8 (packed f32x2).
__global__ __launch_bounds__(256) void attn_kernel(
    const int* __restrict__ adj, float* __restrict__ out)
{
    __shared__ float s_src[32], s_P1[32], s_P2[32];
    __shared__ float s_prob[32][36];   // [j][i], pad 36 -> conflict-lite STS, 16B-aligned rows
    __shared__ float s_feat[32][64];   // [j][cg]
    __shared__ float s_sum[32];

    const int h  = blockIdx.x;
    const int i0 = blockIdx.y * 32;
    const int tid = threadIdx.x;
    const int cg = tid & 63;           // column within head
    const int ig = tid >> 6;           // 0..3 -> i block of 8
    const int jj = tid & 31;           // j lane for prob compute
    const int wp = tid >> 5;           // warp id 0..7 -> i4

    if (tid < 32) {
        float src = g_src[(i0 + tid) * NH + h];
        float md = fdec(g_maxdst_enc[h]);
        float bb = src + md;
        bb = (bb >= 0.f) ? bb : ALPHA * bb;     // b_i = leaky(src + max_dst) >= all logits
        s_src[tid] = src;
        s_P1[tid] = expf(src - bb);
        s_P2[tid] = expf(ALPHA * src - bb);
    }
    __syncthreads();

    unsigned long long acc[4] = {0ull, 0ull, 0ull, 0ull};  // 8 fp32 accumulators, packed
    float psum[4] = {0.f, 0.f, 0.f, 0.f};

    const float* fbase = g_feats + h * 64 + cg;

    for (int jc = 0; jc < N_NODES / 32; jc++) {
        const int j0 = jc * 32;

        // ---- stage feats chunk [32][64] ----
#pragma unroll
        for (int r = 0; r < 8; r++) {
            int j = r * 4 + ig;
            s_feat[j][cg] = fbase[(size_t)(j0 + j) * C];
        }

        // ---- compute probs [32j][32i] for this head ----
        {
            int g = (j0 + jj) * NH + h;
            float d  = g_dst[g];
            float e1 = g_E1[g];
            float e2 = g_E2[g];
#pragma unroll
            for (int ii = 0; ii < 4; ii++) {
                int i = wp + 8 * ii;
                int av = adj[(size_t)(i0 + i) * N_NODES + j0 + jj];
                float s = s_src[i] + d;
                float p = (av == 1)
                            ? ((s >= 0.f) ? s_P1[i] * e1 : s_P2[i] * e2)
                            : 0.f;
                s_prob[jj][i] = p;
                psum[ii] += p;
            }
        }
        __syncthreads();

        // ---- PV accumulate: packed fp32 FMA (fma.rn.f32x2) ----
#pragma unroll 8
        for (int j = 0; j < 32; j++) {
            float fv = s_feat[j][cg];
            unsigned long long ff;
            asm("mov.b64 %0, {%1, %1};" : "=l"(ff) : "f"(fv));
            const unsigned long long* pr =
                (const unsigned long long*)&s_prob[j][ig * 8];
            unsigned long long p0 = pr[0], p1 = pr[1], p2 = pr[2], p3 = pr[3];
            asm("fma.rn.f32x2 %0, %1, %2, %0;" : "+l"(acc[0]) : "l"(p0), "l"(ff));
            asm("fma.rn.f32x2 %0, %1, %2, %0;" : "+l"(acc[1]) : "l"(p1), "l"(ff));
            asm("fma.rn.f32x2 %0, %1, %2, %0;" : "+l"(acc[2]) : "l"(p2), "l"(ff));
            asm("fma.rn.f32x2 %0, %1, %2, %0;" : "+l"(acc[3]) : "l"(p3), "l"(ff));
        }
        __syncthreads();
    }

    // ---- reduce denominators: warp wp holds i = wp + 8*ii across jj lanes ----
#pragma unroll
    for (int ii = 0; ii < 4; ii++) {
        float v = psum[ii];
#pragma unroll
        for (int o = 16; o; o >>= 1) v += __shfl_xor_sync(0xFFFFFFFFu, v, o);
        if (jj == 0) s_sum[wp + 8 * ii] = v;
    }
    __syncthreads();

    // ---- write normalized output ----
#pragma unroll
    for (int k = 0; k < 4; k++) {
        float lo, hi;
        asm("mov.b64 {%0, %1}, %2;" : "=f"(lo), "=f"(hi) : "l"(acc[k]));
        int iA = ig * 8 + 2 * k;
        int iB = iA + 1;
        out[(size_t)(i0 + iA) * C + h * 64 + cg] = lo / s_sum[iA];
        out[(size_t)(i0 + iB) * C + h * 64 + cg] = hi / s_sum[iB];
    }
}

// ---------------- launch ----------------
extern "C" void kernel_launch(void* const* d_in, const int* in_sizes, int n_in,
                              void* d_out, int out_size)
{
    const float* node_feats = (const float*)d_in[0];
    const int*   adj        = (const int*)d_in[1];
    const float* W          = (const float*)d_in[2];
    const float* b          = (const float*)d_in[3];
    const float* a          = (const float*)d_in[4];
    float* out = (float*)d_out;

    init_kernel<<<1, 32>>>();
    gemm_feats<<<dim3(C / 64, N_NODES / 64), 256>>>(node_feats, W, b);
    srcdst_kernel<<<N_NODES / 8, 256>>>(a);
    attn_kernel<<<dim3(NH, N_NODES / 32), 256>>>(adj, out);
}

// round 4
// speedup vs baseline: 1.0284x; 1.0028x over previous
#include <cuda_runtime.h>
#include <math.h>

#define N_NODES 4096
#define C 256
#define NH 4
#define CH 64
#define ALPHA 0.2f

// ---------------- device scratch (no allocs allowed) ----------------
__device__ float g_feats[N_NODES * C];          // 4 MB
__device__ float g_src[N_NODES * NH];
__device__ float g_dst[N_NODES * NH];
__device__ float g_E1[N_NODES * NH];            // exp(dst)
__device__ float g_E2[N_NODES * NH];            // exp(alpha*dst)
__device__ unsigned int g_maxdst_enc[NH];       // monotone-encoded float max

// monotone encoding of float for atomicMax on unsigned
__device__ __forceinline__ unsigned int fenc(float f) {
    unsigned int u = __float_as_uint(f);
    return (u & 0x80000000u) ? ~u : (u | 0x80000000u);
}
__device__ __forceinline__ float fdec(unsigned int u) {
    return (u & 0x80000000u) ? __uint_as_float(u ^ 0x80000000u)
                             : __uint_as_float(~u);
}

// ---------------- init ----------------
__global__ void init_kernel() {
    if (threadIdx.x < NH) g_maxdst_enc[threadIdx.x] = 0u;  // below enc(-inf)
}

// ---------------- phase 1: feats = X @ W + b ----------------
// X [4096,256], W [256,256], tiles 64x64, BK=16, 256 threads, 4x4 microtile
__global__ __launch_bounds__(256) void gemm_feats(
    const float* __restrict__ X, const float* __restrict__ W,
    const float* __restrict__ bias)
{
    __shared__ float As[16][64];
    __shared__ float Bs[16][64];

    const int tid = threadIdx.x;
    const int tx = tid & 15;
    const int ty = tid >> 4;
    const int bm = blockIdx.y * 64;
    const int bn = blockIdx.x * 64;

    float acc[4][4] = {};

    for (int k0 = 0; k0 < C; k0 += 16) {
        // load A tile (64 rows x 16 k), transposed store
        {
            int row = tid >> 2;            // 0..63
            int kc  = (tid & 3) * 4;       // 0,4,8,12
            float4 v = *(const float4*)&X[(size_t)(bm + row) * C + k0 + kc];
            As[kc + 0][row] = v.x;
            As[kc + 1][row] = v.y;
            As[kc + 2][row] = v.z;
            As[kc + 3][row] = v.w;
        }
        // load B tile (16 k x 64 cols)
        {
            int kr = tid >> 4;             // 0..15
            int cc = (tid & 15) * 4;       // 0..60
            *(float4*)&Bs[kr][cc] =
                *(const float4*)&W[(size_t)(k0 + kr) * C + bn + cc];
        }
        __syncthreads();

#pragma unroll
        for (int kk = 0; kk < 16; kk++) {
            float4 a4 = *(const float4*)&As[kk][ty * 4];
            float4 b4 = *(const float4*)&Bs[kk][tx * 4];
            float av[4] = {a4.x, a4.y, a4.z, a4.w};
            float bv[4] = {b4.x, b4.y, b4.z, b4.w};
#pragma unroll
            for (int i = 0; i < 4; i++)
#pragma unroll
                for (int j = 0; j < 4; j++)
                    acc[i][j] += av[i] * bv[j];
        }
        __syncthreads();
    }

#pragma unroll
    for (int i = 0; i < 4; i++) {
#pragma unroll
        for (int j = 0; j < 4; j++) {
            int r = bm + ty * 4 + i;
            int c = bn + tx * 4 + j;
            g_feats[(size_t)r * C + c] = acc[i][j] + bias[c];
        }
    }
}

// ---------------- phase 2: src/dst + exp factors + maxdst ----------------
// one warp per node; a is [NH][2*CH] = [4][128]
__global__ __launch_bounds__(256) void srcdst_kernel(const float* __restrict__ a)
{
    const int warp = threadIdx.x >> 5;
    const int lane = threadIdx.x & 31;
    const int n = blockIdx.x * 8 + warp;
    if (n >= N_NODES) return;

    const float* f = g_feats + (size_t)n * C;

#pragma unroll
    for (int h = 0; h < NH; h++) {
        float f0 = f[h * 64 + lane];
        float f1 = f[h * 64 + 32 + lane];
        float as0 = a[h * 128 + lane];
        float as1 = a[h * 128 + 32 + lane];
        float ad0 = a[h * 128 + 64 + lane];
        float ad1 = a[h * 128 + 96 + lane];
        float vs = f0 * as0 + f1 * as1;
        float vd = f0 * ad0 + f1 * ad1;
#pragma unroll
        for (int o = 16; o; o >>= 1) {
            vs += __shfl_xor_sync(0xFFFFFFFFu, vs, o);
            vd += __shfl_xor_sync(0xFFFFFFFFu, vd, o);
        }
        if (lane == 0) {
            g_src[n * NH + h] = vs;
            g_dst[n * NH + h] = vd;
            g_E1[n * NH + h] = expf(vd);
            g_E2[n * NH + h] = expf(ALPHA * vd);
            atomicMax(&g_maxdst_enc[h], fenc(vd));
        }
    }
}

// ---------------- phase 3: masked-softmax attention + PV (fused) ----------------
// grid (NH, N/32); block 256 threads; head fastest for adj L2 reuse.
// Thread t: column cg = t&63 of its head, i-range = (t>>6)*8 .. +8 (packed f32x2).
__global__ __launch_bounds__(256) void attn_kernel(
    const int* __restrict__ adj, float* __restrict__ out)
{
    __shared__ float s_src[32], s_P1[32], s_P2[32];
    __shared__ float s_prob[32][36];   // [j][i], pad 36 -> conflict-lite STS, 16B-aligned rows
    __shared__ float s_feat[32][64];   // [j][cg]
    __shared__ float s_sum[32];

    const int h  = blockIdx.x;
    const int i0 = blockIdx.y * 32;
    const int tid = threadIdx.x;
    const int cg = tid & 63;           // column within head
    const int ig = tid >> 6;           // 0..3 -> i block of 8
    const int jj = tid & 31;           // j lane for prob compute
    const int wp = tid >> 5;           // warp id 0..7 -> i4

    if (tid < 32) {
        float src = g_src[(i0 + tid) * NH + h];
        float md = fdec(g_maxdst_enc[h]);
        float bb = src + md;
        bb = (bb >= 0.f) ? bb : ALPHA * bb;     // b_i = leaky(src + max_dst) >= all logits
        s_src[tid] = src;
        s_P1[tid] = expf(src - bb);
        s_P2[tid] = expf(ALPHA * src - bb);
    }
    __syncthreads();

    unsigned long long acc[4] = {0ull, 0ull, 0ull, 0ull};  // 8 fp32 accumulators, packed
    float psum[4] = {0.f, 0.f, 0.f, 0.f};

    const float* fbase = g_feats + h * 64 + cg;

    for (int jc = 0; jc < N_NODES / 32; jc++) {
        const int j0 = jc * 32;

        // ---- stage feats chunk [32][64] ----
#pragma unroll
        for (int r = 0; r < 8; r++) {
            int j = r * 4 + ig;
            s_feat[j][cg] = fbase[(size_t)(j0 + j) * C];
        }

        // ---- compute probs [32j][32i] for this head ----
        {
            int g = (j0 + jj) * NH + h;
            float d  = g_dst[g];
            float e1 = g_E1[g];
            float e2 = g_E2[g];
#pragma unroll
            for (int ii = 0; ii < 4; ii++) {
                int i = wp + 8 * ii;
                int av = adj[(size_t)(i0 + i) * N_NODES + j0 + jj];
                float s = s_src[i] + d;
                float p = (av == 1)
                            ? ((s >= 0.f) ? s_P1[i] * e1 : s_P2[i] * e2)
                            : 0.f;
                s_prob[jj][i] = p;
                psum[ii] += p;
            }
        }
        __syncthreads();

        // ---- PV accumulate: packed fp32 FMA (fma.rn.f32x2) ----
#pragma unroll 8
        for (int j = 0; j < 32; j++) {
            float fv = s_feat[j][cg];
            unsigned long long ff;
            asm("mov.b64 %0, {%1, %1};" : "=l"(ff) : "f"(fv));
            const unsigned long long* pr =
                (const unsigned long long*)&s_prob[j][ig * 8];
            unsigned long long p0 = pr[0], p1 = pr[1], p2 = pr[2], p3 = pr[3];
            asm("fma.rn.f32x2 %0, %1, %2, %0;" : "+l"(acc[0]) : "l"(p0), "l"(ff));
            asm("fma.rn.f32x2 %0, %1, %2, %0;" : "+l"(acc[1]) : "l"(p1), "l"(ff));
            asm("fma.rn.f32x2 %0, %1, %2, %0;" : "+l"(acc[2]) : "l"(p2), "l"(ff));
            asm("fma.rn.f32x2 %0, %1, %2, %0;" : "+l"(acc[3]) : "l"(p3), "l"(ff));
        }
        __syncthreads();
    }

    // ---- reduce denominators: warp wp holds i = wp + 8*ii across jj lanes ----
#pragma unroll
    for (int ii = 0; ii < 4; ii++) {
        float v = psum[ii];
#pragma unroll
        for (int o = 16; o; o >>= 1) v += __shfl_xor_sync(0xFFFFFFFFu, v, o);
        if (jj == 0) s_sum[wp + 8 * ii] = v;
    }
    __syncthreads();

    // ---- write normalized output ----
#pragma unroll
    for (int k = 0; k < 4; k++) {
        float lo, hi;
        asm("mov.b64 {%0, %1}, %2;" : "=f"(lo), "=f"(hi) : "l"(acc[k]));
        int iA = ig * 8 + 2 * k;
        int iB = iA + 1;
        out[(size_t)(i0 + iA) * C + h * 64 + cg] = lo / s_sum[iA];
        out[(size_t)(i0 + iB) * C + h * 64 + cg] = hi / s_sum[iB];
    }
}

// ---------------- launch ----------------
extern "C" void kernel_launch(void* const* d_in, const int* in_sizes, int n_in,
                              void* d_out, int out_size)
{
    const float* node_feats = (const float*)d_in[0];
    const int*   adj        = (const int*)d_in[1];
    const float* W          = (const float*)d_in[2];
    const float* b          = (const float*)d_in[3];
    const float* a          = (const float*)d_in[4];
    float* out = (float*)d_out;

    init_kernel<<<1, 32>>>();
    gemm_feats<<<dim3(C / 64, N_NODES / 64), 256>>>(node_feats, W, b);
    srcdst_kernel<<<N_NODES / 8, 256>>>(a);
    attn_kernel<<<dim3(NH, N_NODES / 32), 256>>>(adj, out);
}

// round 5
// speedup vs baseline: 1.0299x; 1.0015x over previous
#include <cuda_runtime.h>
#include <math.h>

#define N_NODES 4096
#define C 256
#define NH 4
#define CH 64
#define ALPHA 0.2f

// ---------------- device scratch (no allocs allowed) ----------------
__device__ float g_feats[N_NODES * C];          // 4 MB
__device__ float g_src[N_NODES * NH];
__device__ float g_dst[N_NODES * NH];
__device__ float g_E1[N_NODES * NH];            // exp(dst)
__device__ float g_E2[N_NODES * NH];            // exp(alpha*dst)
__device__ unsigned int g_maxdst_enc[NH];       // monotone-encoded float max

// monotone encoding of float for atomicMax on unsigned
__device__ __forceinline__ unsigned int fenc(float f) {
    unsigned int u = __float_as_uint(f);
    return (u & 0x80000000u) ? ~u : (u | 0x80000000u);
}
__device__ __forceinline__ float fdec(unsigned int u) {
    return (u & 0x80000000u) ? __uint_as_float(u ^ 0x80000000u)
                             : __uint_as_float(~u);
}

// ---------------- init ----------------
__global__ void init_kernel() {
    if (threadIdx.x < NH) g_maxdst_enc[threadIdx.x] = 0u;  // below enc(-inf)
}

// ---------------- phase 1: feats = X @ W + b ----------------
// X [4096,256], W [256,256], tiles 64x64, BK=16, 256 threads, 4x4 microtile
__global__ __launch_bounds__(256) void gemm_feats(
    const float* __restrict__ X, const float* __restrict__ W,
    const float* __restrict__ bias)
{
    __shared__ float As[16][64];
    __shared__ float Bs[16][64];

    const int tid = threadIdx.x;
    const int tx = tid & 15;
    const int ty = tid >> 4;
    const int bm = blockIdx.y * 64;
    const int bn = blockIdx.x * 64;

    float acc[4][4] = {};

    for (int k0 = 0; k0 < C; k0 += 16) {
        // load A tile (64 rows x 16 k), transposed store
        {
            int row = tid >> 2;            // 0..63
            int kc  = (tid & 3) * 4;       // 0,4,8,12
            float4 v = *(const float4*)&X[(size_t)(bm + row) * C + k0 + kc];
            As[kc + 0][row] = v.x;
            As[kc + 1][row] = v.y;
            As[kc + 2][row] = v.z;
            As[kc + 3][row] = v.w;
        }
        // load B tile (16 k x 64 cols)
        {
            int kr = tid >> 4;             // 0..15
            int cc = (tid & 15) * 4;       // 0..60
            *(float4*)&Bs[kr][cc] =
                *(const float4*)&W[(size_t)(k0 + kr) * C + bn + cc];
        }
        __syncthreads();

#pragma unroll
        for (int kk = 0; kk < 16; kk++) {
            float4 a4 = *(const float4*)&As[kk][ty * 4];
            float4 b4 = *(const float4*)&Bs[kk][tx * 4];
            float av[4] = {a4.x, a4.y, a4.z, a4.w};
            float bv[4] = {b4.x, b4.y, b4.z, b4.w};
#pragma unroll
            for (int i = 0; i < 4; i++)
#pragma unroll
                for (int j = 0; j < 4; j++)
                    acc[i][j] += av[i] * bv[j];
        }
        __syncthreads();
    }

#pragma unroll
    for (int i = 0; i < 4; i++) {
#pragma unroll
        for (int j = 0; j < 4; j++) {
            int r = bm + ty * 4 + i;
            int c = bn + tx * 4 + j;
            g_feats[(size_t)r * C + c] = acc[i][j] + bias[c];
        }
    }
}

// ---------------- phase 2: src/dst + exp factors + maxdst ----------------
// one warp per node; a is [NH][2*CH] = [4][128]
__global__ __launch_bounds__(256) void srcdst_kernel(const float* __restrict__ a)
{
    const int warp = threadIdx.x >> 5;
    const int lane = threadIdx.x & 31;
    const int n = blockIdx.x * 8 + warp;
    if (n >= N_NODES) return;

    const float* f = g_feats + (size_t)n * C;

#pragma unroll
    for (int h = 0; h < NH; h++) {
        float f0 = f[h * 64 + lane];
        float f1 = f[h * 64 + 32 + lane];
        float as0 = a[h * 128 + lane];
        float as1 = a[h * 128 + 32 + lane];
        float ad0 = a[h * 128 + 64 + lane];
        float ad1 = a[h * 128 + 96 + lane];
        float vs = f0 * as0 + f1 * as1;
        float vd = f0 * ad0 + f1 * ad1;
#pragma unroll
        for (int o = 16; o; o >>= 1) {
            vs += __shfl_xor_sync(0xFFFFFFFFu, vs, o);
            vd += __shfl_xor_sync(0xFFFFFFFFu, vd, o);
        }
        if (lane == 0) {
            g_src[n * NH + h] = vs;
            g_dst[n * NH + h] = vd;
            g_E1[n * NH + h] = expf(vd);
            g_E2[n * NH + h] = expf(ALPHA * vd);
            atomicMax(&g_maxdst_enc[h], fenc(vd));
        }
    }
}

// ---------------- phase 3: masked-softmax attention + PV (fused) ----------------
// grid (NH, N/32); block 256 threads; head fastest for adj L2 reuse.
// Thread t: column cg = t&63 of its head, i-range = (t>>6)*8 .. +8 (packed f32x2).
__global__ __launch_bounds__(256) void attn_kernel(
    const int* __restrict__ adj, float* __restrict__ out)
{
    __shared__ float s_src[32], s_P1[32], s_P2[32];
    __shared__ float s_prob[32][36];   // [j][i], pad 36 -> conflict-lite STS, 16B-aligned rows
    __shared__ float s_feat[32][64];   // [j][cg]
    __shared__ float s_sum[32];

    const int h  = blockIdx.x;
    const int i0 = blockIdx.y * 32;
    const int tid = threadIdx.x;
    const int cg = tid & 63;           // column within head
    const int ig = tid >> 6;           // 0..3 -> i block of 8
    const int jj = tid & 31;           // j lane for prob compute
    const int wp = tid >> 5;           // warp id 0..7 -> i4

    if (tid < 32) {
        float src = g_src[(i0 + tid) * NH + h];
        float md = fdec(g_maxdst_enc[h]);
        float bb = src + md;
        bb = (bb >= 0.f) ? bb : ALPHA * bb;     // b_i = leaky(src + max_dst) >= all logits
        s_src[tid] = src;
        s_P1[tid] = expf(src - bb);
        s_P2[tid] = expf(ALPHA * src - bb);
    }
    __syncthreads();

    unsigned long long acc[4] = {0ull, 0ull, 0ull, 0ull};  // 8 fp32 accumulators, packed
    float psum[4] = {0.f, 0.f, 0.f, 0.f};

    const float* fbase = g_feats + h * 64 + cg;

    for (int jc = 0; jc < N_NODES / 32; jc++) {
        const int j0 = jc * 32;

        // ---- stage feats chunk [32][64] ----
#pragma unroll
        for (int r = 0; r < 8; r++) {
            int j = r * 4 + ig;
            s_feat[j][cg] = fbase[(size_t)(j0 + j) * C];
        }

        // ---- compute probs [32j][32i] for this head ----
        {
            int g = (j0 + jj) * NH + h;
            float d  = g_dst[g];
            float e1 = g_E1[g];
            float e2 = g_E2[g];
#pragma unroll
            for (int ii = 0; ii < 4; ii++) {
                int i = wp + 8 * ii;
                int av = adj[(size_t)(i0 + i) * N_NODES + j0 + jj];
                float s = s_src[i] + d;
                float p = (av == 1)
                            ? ((s >= 0.f) ? s_P1[i] * e1 : s_P2[i] * e2)
                            : 0.f;
                s_prob[jj][i] = p;
                psum[ii] += p;
            }
        }
        __syncthreads();

        // ---- PV accumulate: packed fp32 FMA (fma.rn.f32x2) ----
#pragma unroll 8
        for (int j = 0; j < 32; j++) {
            float fv = s_feat[j][cg];
            unsigned long long ff;
            asm("mov.b64 %0, {%1, %1};" : "=l"(ff) : "f"(fv));
            const unsigned long long* pr =
                (const unsigned long long*)&s_prob[j][ig * 8];
            unsigned long long p0 = pr[0], p1 = pr[1], p2 = pr[2], p3 = pr[3];
            asm("fma.rn.f32x2 %0, %1, %2, %0;" : "+l"(acc[0]) : "l"(p0), "l"(ff));
            asm("fma.rn.f32x2 %0, %1, %2, %0;" : "+l"(acc[1]) : "l"(p1), "l"(ff));
            asm("fma.rn.f32x2 %0, %1, %2, %0;" : "+l"(acc[2]) : "l"(p2), "l"(ff));
            asm("fma.rn.f32x2 %0, %1, %2, %0;" : "+l"(acc[3]) : "l"(p3), "l"(ff));
        }
        __syncthreads();
    }

    // ---- reduce denominators: warp wp holds i = wp + 8*ii across jj lanes ----
#pragma unroll
    for (int ii = 0; ii < 4; ii++) {
        float v = psum[ii];
#pragma unroll
        for (int o = 16; o; o >>= 1) v += __shfl_xor_sync(0xFFFFFFFFu, v, o);
        if (jj == 0) s_sum[wp + 8 * ii] = v;
    }
    __syncthreads();

    // ---- write normalized output ----
#pragma unroll
    for (int k = 0; k < 4; k++) {
        float lo, hi;
        asm("mov.b64 {%0, %1}, %2;" : "=f"(lo), "=f"(hi) : "l"(acc[k]));
        int iA = ig * 8 + 2 * k;
        int iB = iA + 1;
        out[(size_t)(i0 + iA) * C + h * 64 + cg] = lo / s_sum[iA];
        out[(size_t)(i0 + iB) * C + h * 64 + cg] = hi / s_sum[iB];
    }
}

// ---------------- launch ----------------
extern "C" void kernel_launch(void* const* d_in, const int* in_sizes, int n_in,
                              void* d_out, int out_size)
{
    const float* node_feats = (const float*)d_in[0];
    const int*   adj        = (const int*)d_in[1];
    const float* W          = (const float*)d_in[2];
    const float* b          = (const float*)d_in[3];
    const float* a          = (const float*)d_in[4];
    float* out = (float*)d_out;

    init_kernel<<<1, 32>>>();
    gemm_feats<<<dim3(C / 64, N_NODES / 64), 256>>>(node_feats, W, b);
    srcdst_kernel<<<N_NODES / 8, 256>>>(a);
    attn_kernel<<<dim3(NH, N_NODES / 32), 256>>>(adj, out);
}

// round 6
// speedup vs baseline: 1.0335x; 1.0035x over previous
#include <cuda_runtime.h>
#include <math.h>

#define N_NODES 4096
#define C 256
#define NH 4
#define CH 64
#define ALPHA 0.2f

// ---------------- device scratch (no allocs allowed) ----------------
__device__ float g_feats[N_NODES * C];          // 4 MB
__device__ float g_src[N_NODES * NH];
__device__ float g_dst[N_NODES * NH];
__device__ float g_E1[N_NODES * NH];            // exp(dst)
__device__ float g_E2[N_NODES * NH];            // exp(alpha*dst)
__device__ unsigned int g_maxdst_enc[NH];       // monotone-encoded float max

// monotone encoding of float for atomicMax on unsigned
__device__ __forceinline__ unsigned int fenc(float f) {
    unsigned int u = __float_as_uint(f);
    return (u & 0x80000000u) ? ~u : (u | 0x80000000u);
}
__device__ __forceinline__ float fdec(unsigned int u) {
    return (u & 0x80000000u) ? __uint_as_float(u ^ 0x80000000u)
                             : __uint_as_float(~u);
}

// ---------------- init ----------------
__global__ void init_kernel() {
    if (threadIdx.x < NH) g_maxdst_enc[threadIdx.x] = 0u;  // below enc(-inf)
}

// ---------------- phase 1: feats = X @ W + b ----------------
// X [4096,256], W [256,256], tiles 64x64, BK=16, 256 threads, 4x4 microtile
__global__ __launch_bounds__(256) void gemm_feats(
    const float* __restrict__ X, const float* __restrict__ W,
    const float* __restrict__ bias)
{
    __shared__ float As[16][64];
    __shared__ float Bs[16][64];

    const int tid = threadIdx.x;
    const int tx = tid & 15;
    const int ty = tid >> 4;
    const int bm = blockIdx.y * 64;
    const int bn = blockIdx.x * 64;

    float acc[4][4] = {};

    for (int k0 = 0; k0 < C; k0 += 16) {
        // load A tile (64 rows x 16 k), transposed store
        {
            int row = tid >> 2;            // 0..63
            int kc  = (tid & 3) * 4;       // 0,4,8,12
            float4 v = *(const float4*)&X[(size_t)(bm + row) * C + k0 + kc];
            As[kc + 0][row] = v.x;
            As[kc + 1][row] = v.y;
            As[kc + 2][row] = v.z;
            As[kc + 3][row] = v.w;
        }
        // load B tile (16 k x 64 cols)
        {
            int kr = tid >> 4;             // 0..15
            int cc = (tid & 15) * 4;       // 0..60
            *(float4*)&Bs[kr][cc] =
                *(const float4*)&W[(size_t)(k0 + kr) * C + bn + cc];
        }
        __syncthreads();

#pragma unroll
        for (int kk = 0; kk < 16; kk++) {
            float4 a4 = *(const float4*)&As[kk][ty * 4];
            float4 b4 = *(const float4*)&Bs[kk][tx * 4];
            float av[4] = {a4.x, a4.y, a4.z, a4.w};
            float bv[4] = {b4.x, b4.y, b4.z, b4.w};
#pragma unroll
            for (int i = 0; i < 4; i++)
#pragma unroll
                for (int j = 0; j < 4; j++)
                    acc[i][j] += av[i] * bv[j];
        }
        __syncthreads();
    }

#pragma unroll
    for (int i = 0; i < 4; i++) {
#pragma unroll
        for (int j = 0; j < 4; j++) {
            int r = bm + ty * 4 + i;
            int c = bn + tx * 4 + j;
            g_feats[(size_t)r * C + c] = acc[i][j] + bias[c];
        }
    }
}

// ---------------- phase 2: src/dst + exp factors + maxdst ----------------
// one warp per node; a is [NH][2*CH] = [4][128]
__global__ __launch_bounds__(256) void srcdst_kernel(const float* __restrict__ a)
{
    const int warp = threadIdx.x >> 5;
    const int lane = threadIdx.x & 31;
    const int n = blockIdx.x * 8 + warp;
    if (n >= N_NODES) return;

    const float* f = g_feats + (size_t)n * C;

#pragma unroll
    for (int h = 0; h < NH; h++) {
        float f0 = f[h * 64 + lane];
        float f1 = f[h * 64 + 32 + lane];
        float as0 = a[h * 128 + lane];
        float as1 = a[h * 128 + 32 + lane];
        float ad0 = a[h * 128 + 64 + lane];
        float ad1 = a[h * 128 + 96 + lane];
        float vs = f0 * as0 + f1 * as1;
        float vd = f0 * ad0 + f1 * ad1;
#pragma unroll
        for (int o = 16; o; o >>= 1) {
            vs += __shfl_xor_sync(0xFFFFFFFFu, vs, o);
            vd += __shfl_xor_sync(0xFFFFFFFFu, vd, o);
        }
        if (lane == 0) {
            g_src[n * NH + h] = vs;
            g_dst[n * NH + h] = vd;
            g_E1[n * NH + h] = expf(vd);
            g_E2[n * NH + h] = expf(ALPHA * vd);
            atomicMax(&g_maxdst_enc[h], fenc(vd));
        }
    }
}

// ---------------- phase 3: masked-softmax attention + PV (fused) ----------------
// grid (NH, N/32); block 256 threads; head fastest for adj L2 reuse.
// Thread t: column cg = t&63 of its head, i-range = (t>>6)*8 .. +8 (packed f32x2).
__global__ __launch_bounds__(256) void attn_kernel(
    const int* __restrict__ adj, float* __restrict__ out)
{
    __shared__ float s_src[32], s_P1[32], s_P2[32];
    __shared__ float s_prob[32][36];   // [j][i], pad 36 -> conflict-lite STS, 16B-aligned rows
    __shared__ float s_feat[32][64];   // [j][cg]
    __shared__ float s_sum[32];

    const int h  = blockIdx.x;
    const int i0 = blockIdx.y * 32;
    const int tid = threadIdx.x;
    const int cg = tid & 63;           // column within head
    const int ig = tid >> 6;           // 0..3 -> i block of 8
    const int jj = tid & 31;           // j lane for prob compute
    const int wp = tid >> 5;           // warp id 0..7 -> i4

    if (tid < 32) {
        float src = g_src[(i0 + tid) * NH + h];
        float md = fdec(g_maxdst_enc[h]);
        float bb = src + md;
        bb = (bb >= 0.f) ? bb : ALPHA * bb;     // b_i = leaky(src + max_dst) >= all logits
        s_src[tid] = src;
        s_P1[tid] = expf(src - bb);
        s_P2[tid] = expf(ALPHA * src - bb);
    }
    __syncthreads();

    unsigned long long acc[4] = {0ull, 0ull, 0ull, 0ull};  // 8 fp32 accumulators, packed
    float psum[4] = {0.f, 0.f, 0.f, 0.f};

    const float* fbase = g_feats + h * 64 + cg;

    for (int jc = 0; jc < N_NODES / 32; jc++) {
        const int j0 = jc * 32;

        // ---- stage feats chunk [32][64] ----
#pragma unroll
        for (int r = 0; r < 8; r++) {
            int j = r * 4 + ig;
            s_feat[j][cg] = fbase[(size_t)(j0 + j) * C];
        }

        // ---- compute probs [32j][32i] for this head ----
        {
            int g = (j0 + jj) * NH + h;
            float d  = g_dst[g];
            float e1 = g_E1[g];
            float e2 = g_E2[g];
#pragma unroll
            for (int ii = 0; ii < 4; ii++) {
                int i = wp + 8 * ii;
                int av = adj[(size_t)(i0 + i) * N_NODES + j0 + jj];
                float s = s_src[i] + d;
                float p = (av == 1)
                            ? ((s >= 0.f) ? s_P1[i] * e1 : s_P2[i] * e2)
                            : 0.f;
                s_prob[jj][i] = p;
                psum[ii] += p;
            }
        }
        __syncthreads();

        // ---- PV accumulate: packed fp32 FMA (fma.rn.f32x2) ----
#pragma unroll 8
        for (int j = 0; j < 32; j++) {
            float fv = s_feat[j][cg];
            unsigned long long ff;
            asm("mov.b64 %0, {%1, %1};" : "=l"(ff) : "f"(fv));
            const unsigned long long* pr =
                (const unsigned long long*)&s_prob[j][ig * 8];
            unsigned long long p0 = pr[0], p1 = pr[1], p2 = pr[2], p3 = pr[3];
            asm("fma.rn.f32x2 %0, %1, %2, %0;" : "+l"(acc[0]) : "l"(p0), "l"(ff));
            asm("fma.rn.f32x2 %0, %1, %2, %0;" : "+l"(acc[1]) : "l"(p1), "l"(ff));
            asm("fma.rn.f32x2 %0, %1, %2, %0;" : "+l"(acc[2]) : "l"(p2), "l"(ff));
            asm("fma.rn.f32x2 %0, %1, %2, %0;" : "+l"(acc[3]) : "l"(p3), "l"(ff));
        }
        __syncthreads();
    }

    // ---- reduce denominators: warp wp holds i = wp + 8*ii across jj lanes ----
#pragma unroll
    for (int ii = 0; ii < 4; ii++) {
        float v = psum[ii];
#pragma unroll
        for (int o = 16; o; o >>= 1) v += __shfl_xor_sync(0xFFFFFFFFu, v, o);
        if (jj == 0) s_sum[wp + 8 * ii] = v;
    }
    __syncthreads();

    // ---- write normalized output ----
#pragma unroll
    for (int k = 0; k < 4; k++) {
        float lo, hi;
        asm("mov.b64 {%0, %1}, %2;" : "=f"(lo), "=f"(hi) : "l"(acc[k]));
        int iA = ig * 8 + 2 * k;
        int iB = iA + 1;
        out[(size_t)(i0 + iA) * C + h * 64 + cg] = lo / s_sum[iA];
        out[(size_t)(i0 + iB) * C + h * 64 + cg] = hi / s_sum[iB];
    }
}

// ---------------- launch ----------------
extern "C" void kernel_launch(void* const* d_in, const int* in_sizes, int n_in,
                              void* d_out, int out_size)
{
    const float* node_feats = (const float*)d_in[0];
    const int*   adj        = (const int*)d_in[1];
    const float* W          = (const float*)d_in[2];
    const float* b          = (const float*)d_in[3];
    const float* a          = (const float*)d_in[4];
    float* out = (float*)d_out;

    init_kernel<<<1, 32>>>();
    gemm_feats<<<dim3(C / 64, N_NODES / 64), 256>>>(node_feats, W, b);
    srcdst_kernel<<<N_NODES / 8, 256>>>(a);
    attn_kernel<<<dim3(NH, N_NODES / 32), 256>>>(adj, out);
}

// round 7
// speedup vs baseline: 1.4331x; 1.3867x over previous
#include <cuda_runtime.h>
#include <math.h>

#define N_NODES 4096
#define C 256
#define NH 4
#define CH 64
#define ALPHA 0.2f

// ---------------- device scratch (no allocs allowed) ----------------
__device__ float g_feats[N_NODES * C];          // 4 MB
__device__ float g_src[N_NODES * NH];
__device__ float g_dst[N_NODES * NH];
__device__ float g_E1[N_NODES * NH];            // exp(dst)
__device__ float g_E2[N_NODES * NH];            // exp(alpha*dst)
__device__ unsigned int g_maxdst_enc[NH];       // monotone-encoded float max

// monotone encoding of float for atomicMax on unsigned
__device__ __forceinline__ unsigned int fenc(float f) {
    unsigned int u = __float_as_uint(f);
    return (u & 0x80000000u) ? ~u : (u | 0x80000000u);
}
__device__ __forceinline__ float fdec(unsigned int u) {
    return (u & 0x80000000u) ? __uint_as_float(u ^ 0x80000000u)
                             : __uint_as_float(~u);
}

// ---------------- init ----------------
__global__ void init_kernel() {
    if (threadIdx.x < NH) g_maxdst_enc[threadIdx.x] = 0u;  // below enc(-inf)
}

// ---------------- phase 1: feats = X @ W + b ----------------
// X [4096,256], W [256,256], tiles 64x64, BK=16, 256 threads, 4x4 microtile
__global__ __launch_bounds__(256) void gemm_feats(
    const float* __restrict__ X, const float* __restrict__ W,
    const float* __restrict__ bias)
{
    __shared__ float As[16][64];
    __shared__ float Bs[16][64];

    const int tid = threadIdx.x;
    const int tx = tid & 15;
    const int ty = tid >> 4;
    const int bm = blockIdx.y * 64;
    const int bn = blockIdx.x * 64;

    float acc[4][4] = {};

    for (int k0 = 0; k0 < C; k0 += 16) {
        {
            int row = tid >> 2;            // 0..63
            int kc  = (tid & 3) * 4;       // 0,4,8,12
            float4 v = *(const float4*)&X[(size_t)(bm + row) * C + k0 + kc];
            As[kc + 0][row] = v.x;
            As[kc + 1][row] = v.y;
            As[kc + 2][row] = v.z;
            As[kc + 3][row] = v.w;
        }
        {
            int kr = tid >> 4;             // 0..15
            int cc = (tid & 15) * 4;       // 0..60
            *(float4*)&Bs[kr][cc] =
                *(const float4*)&W[(size_t)(k0 + kr) * C + bn + cc];
        }
        __syncthreads();

#pragma unroll
        for (int kk = 0; kk < 16; kk++) {
            float4 a4 = *(const float4*)&As[kk][ty * 4];
            float4 b4 = *(const float4*)&Bs[kk][tx * 4];
            float av[4] = {a4.x, a4.y, a4.z, a4.w};
            float bv[4] = {b4.x, b4.y, b4.z, b4.w};
#pragma unroll
            for (int i = 0; i < 4; i++)
#pragma unroll
                for (int j = 0; j < 4; j++)
                    acc[i][j] += av[i] * bv[j];
        }
        __syncthreads();
    }

#pragma unroll
    for (int i = 0; i < 4; i++) {
#pragma unroll
        for (int j = 0; j < 4; j++) {
            int r = bm + ty * 4 + i;
            int c = bn + tx * 4 + j;
            g_feats[(size_t)r * C + c] = acc[i][j] + bias[c];
        }
    }
}

// ---------------- phase 2: src/dst + exp factors + maxdst ----------------
__global__ __launch_bounds__(256) void srcdst_kernel(const float* __restrict__ a)
{
    const int warp = threadIdx.x >> 5;
    const int lane = threadIdx.x & 31;
    const int n = blockIdx.x * 8 + warp;
    if (n >= N_NODES) return;

    const float* f = g_feats + (size_t)n * C;

#pragma unroll
    for (int h = 0; h < NH; h++) {
        float f0 = f[h * 64 + lane];
        float f1 = f[h * 64 + 32 + lane];
        float as0 = a[h * 128 + lane];
        float as1 = a[h * 128 + 32 + lane];
        float ad0 = a[h * 128 + 64 + lane];
        float ad1 = a[h * 128 + 96 + lane];
        float vs = f0 * as0 + f1 * as1;
        float vd = f0 * ad0 + f1 * ad1;
#pragma unroll
        for (int o = 16; o; o >>= 1) {
            vs += __shfl_xor_sync(0xFFFFFFFFu, vs, o);
            vd += __shfl_xor_sync(0xFFFFFFFFu, vd, o);
        }
        if (lane == 0) {
            g_src[n * NH + h] = vs;
            g_dst[n * NH + h] = vd;
            g_E1[n * NH + h] = expf(vd);
            g_E2[n * NH + h] = expf(ALPHA * vd);
            atomicMax(&g_maxdst_enc[h], fenc(vd));
        }
    }
}

// ---------------- phase 3: masked-softmax attention + PV (fused) ----------------
// grid (NH, N/64); block 128 threads (4 warps).
// Block tile: 64 i x 64 c (full head) x full j loop (chunks of 32 j).
// Thread (jj = tid&31, wp = tid>>5):
//   prob phase : computes probs for j = j0+jj, i = wp*16 .. wp*16+15
//   PV phase   : cols = jj*2, jj*2+1 ; i = wp*16 .. +15 (8 f32x2 pairs x 2 cols)
// Probs stored transposed as quads: s_probQ[i/4][j] (float4) -> broadcast LDS.128
// reads in PV, conflict-free STS.128 writes in prob phase.
__global__ __launch_bounds__(128) void attn_kernel(
    const int* __restrict__ adj, float* __restrict__ out)
{
    __shared__ float4 s_probQ[2][16][32];   // [buf][i-quad][j]   16 KB
    __shared__ float  s_feat[2][32][64];    // [buf][j][c]        16 KB
    __shared__ float4 s_SPP[64];            // (src, P1, P2, -)    1 KB
    __shared__ float  s_isum[64];           // 1/denominator

    const int h   = blockIdx.x;
    const int i0  = blockIdx.y * 64;
    const int tid = threadIdx.x;
    const int jj  = tid & 31;
    const int wp  = tid >> 5;

    if (tid < 64) {
        float src = g_src[(i0 + tid) * NH + h];
        float md  = fdec(g_maxdst_enc[h]);
        float bb  = src + md;
        bb = (bb >= 0.f) ? bb : ALPHA * bb;   // b_i = leaky(src + max_dst) >= all logits
        s_SPP[tid] = make_float4(src, expf(src - bb), expf(ALPHA * src - bb), 0.f);
    }
    __syncthreads();

    unsigned long long acc[8][2];
#pragma unroll
    for (int p = 0; p < 8; p++) { acc[p][0] = 0ull; acc[p][1] = 0ull; }
    float psum[16];
#pragma unroll
    for (int k = 0; k < 16; k++) psum[k] = 0.f;

    const float* fbase = g_feats + h * 64;

    for (int chunk = 0; chunk < N_NODES / 32; chunk++) {
        const int j0  = chunk * 32;
        const int buf = chunk & 1;

        // ---- stage feats chunk [32][64] (float4 loads/stores) ----
#pragma unroll
        for (int m = 0; m < 4; m++) {
            int idx = tid + 128 * m;
            int r   = idx >> 4;
            int cq  = idx & 15;
            float4 v = *(const float4*)&fbase[(size_t)(j0 + r) * C + cq * 4];
            *(float4*)&s_feat[buf][r][cq * 4] = v;
        }

        // ---- probs for j = j0+jj, i = wp*16 .. +15, stored as i-quads ----
        {
            int g    = (j0 + jj) * NH + h;
            float d  = g_dst[g];
            float e1 = g_E1[g];
            float e2 = g_E2[g];
#pragma unroll
            for (int qq = 0; qq < 4; qq++) {
                int q = wp * 4 + qq;
                float pr[4];
#pragma unroll
                for (int k = 0; k < 4; k++) {
                    int i  = q * 4 + k;
                    int av = adj[(size_t)(i0 + i) * N_NODES + j0 + jj];
                    float4 spp = s_SPP[i];
                    float s = spp.x + d;
                    float p = (av == 1)
                                ? ((s >= 0.f) ? spp.y * e1 : spp.z * e2)
                                : 0.f;
                    pr[k] = p;
                    psum[qq * 4 + k] += p;
                }
                s_probQ[buf][q][jj] = make_float4(pr[0], pr[1], pr[2], pr[3]);
            }
        }
        __syncthreads();   // single barrier per chunk (ping-pong buffers)

        // ---- PV: 16 i x 2 c per thread, packed fp32 FMA ----
#pragma unroll 8
        for (int j = 0; j < 32; j++) {
            float2 fp = *(const float2*)&s_feat[buf][j][jj * 2];
            unsigned long long f0, f1;
            asm("mov.b64 %0, {%1, %1};" : "=l"(f0) : "f"(fp.x));
            asm("mov.b64 %0, {%1, %1};" : "=l"(f1) : "f"(fp.y));
#pragma unroll
            for (int qq = 0; qq < 4; qq++) {
                ulonglong2 pq =
                    *(const ulonglong2*)&s_probQ[buf][wp * 4 + qq][j];
                asm("fma.rn.f32x2 %0, %1, %2, %0;"
                    : "+l"(acc[qq * 2 + 0][0]) : "l"(pq.x), "l"(f0));
                asm("fma.rn.f32x2 %0, %1, %2, %0;"
                    : "+l"(acc[qq * 2 + 0][1]) : "l"(pq.x), "l"(f1));
                asm("fma.rn.f32x2 %0, %1, %2, %0;"
                    : "+l"(acc[qq * 2 + 1][0]) : "l"(pq.y), "l"(f0));
                asm("fma.rn.f32x2 %0, %1, %2, %0;"
                    : "+l"(acc[qq * 2 + 1][1]) : "l"(pq.y), "l"(f1));
            }
        }
    }

    // ---- denominators: reduce psum over the 32 jj lanes ----
#pragma unroll
    for (int k = 0; k < 16; k++) {
        float v = psum[k];
#pragma unroll
        for (int o = 16; o; o >>= 1) v += __shfl_xor_sync(0xFFFFFFFFu, v, o);
        if (jj == 0) s_isum[wp * 16 + k] = 1.f / v;
    }
    __syncthreads();

    // ---- write normalized output ----
#pragma unroll
    for (int qq = 0; qq < 4; qq++) {
#pragma unroll
        for (int u = 0; u < 2; u++) {
            int iloc = wp * 16 + qq * 4 + u * 2;
            float r0 = s_isum[iloc];
            float r1 = s_isum[iloc + 1];
#pragma unroll
            for (int c = 0; c < 2; c++) {
                float lo, hi;
                asm("mov.b64 {%0, %1}, %2;"
                    : "=f"(lo), "=f"(hi) : "l"(acc[qq * 2 + u][c]));
                out[(size_t)(i0 + iloc) * C + h * 64 + jj * 2 + c]     = lo * r0;
                out[(size_t)(i0 + iloc + 1) * C + h * 64 + jj * 2 + c] = hi * r1;
            }
        }
    }
}

// ---------------- launch ----------------
extern "C" void kernel_launch(void* const* d_in, const int* in_sizes, int n_in,
                              void* d_out, int out_size)
{
    const float* node_feats = (const float*)d_in[0];
    const int*   adj        = (const int*)d_in[1];
    const float* W          = (const float*)d_in[2];
    const float* b          = (const float*)d_in[3];
    const float* a          = (const float*)d_in[4];
    float* out = (float*)d_out;

    init_kernel<<<1, 32>>>();
    gemm_feats<<<dim3(C / 64, N_NODES / 64), 256>>>(node_feats, W, b);
    srcdst_kernel<<<N_NODES / 8, 256>>>(a);
    attn_kernel<<<dim3(NH, N_NODES / 64), 128>>>(adj, out);
}

// round 8
// speedup vs baseline: 1.5072x; 1.0517x over previous
#include <cuda_runtime.h>
#include <math.h>

#define N_NODES 4096
#define C 256
#define NH 4
#define CH 64
#define ALPHA 0.2f
#define NC (N_NODES / 32)

// ---------------- device scratch (no allocs allowed) ----------------
__device__ float  g_feats[N_NODES * C];     // 4 MB
__device__ float  g_src[N_NODES * NH];
__device__ float4 g_DE[N_NODES * NH];       // (dst, exp(dst), exp(a*dst), -)
__device__ unsigned int g_maxdst_enc[NH];   // monotone-encoded float max

// monotone encoding of float for atomicMax on unsigned
__device__ __forceinline__ unsigned int fenc(float f) {
    unsigned int u = __float_as_uint(f);
    return (u & 0x80000000u) ? ~u : (u | 0x80000000u);
}
__device__ __forceinline__ float fdec(unsigned int u) {
    return (u & 0x80000000u) ? __uint_as_float(u ^ 0x80000000u)
                             : __uint_as_float(~u);
}

// ---------------- init ----------------
__global__ void init_kernel() {
    if (threadIdx.x < NH) g_maxdst_enc[threadIdx.x] = 0u;  // below enc(-inf)
}

// ---------------- phase 1: feats = X @ W + b ----------------
// X [4096,256], W [256,256], tiles 64x64, BK=16, 256 threads, 4x4 microtile
__global__ __launch_bounds__(256) void gemm_feats(
    const float* __restrict__ X, const float* __restrict__ W,
    const float* __restrict__ bias)
{
    __shared__ float As[16][64];
    __shared__ float Bs[16][64];

    const int tid = threadIdx.x;
    const int tx = tid & 15;
    const int ty = tid >> 4;
    const int bm = blockIdx.y * 64;
    const int bn = blockIdx.x * 64;

    float acc[4][4] = {};

    for (int k0 = 0; k0 < C; k0 += 16) {
        {
            int row = tid >> 2;            // 0..63
            int kc  = (tid & 3) * 4;       // 0,4,8,12
            float4 v = *(const float4*)&X[(size_t)(bm + row) * C + k0 + kc];
            As[kc + 0][row] = v.x;
            As[kc + 1][row] = v.y;
            As[kc + 2][row] = v.z;
            As[kc + 3][row] = v.w;
        }
        {
            int kr = tid >> 4;             // 0..15
            int cc = (tid & 15) * 4;       // 0..60
            *(float4*)&Bs[kr][cc] =
                *(const float4*)&W[(size_t)(k0 + kr) * C + bn + cc];
        }
        __syncthreads();

#pragma unroll
        for (int kk = 0; kk < 16; kk++) {
            float4 a4 = *(const float4*)&As[kk][ty * 4];
            float4 b4 = *(const float4*)&Bs[kk][tx * 4];
            float av[4] = {a4.x, a4.y, a4.z, a4.w};
            float bv[4] = {b4.x, b4.y, b4.z, b4.w};
#pragma unroll
            for (int i = 0; i < 4; i++)
#pragma unroll
                for (int j = 0; j < 4; j++)
                    acc[i][j] += av[i] * bv[j];
        }
        __syncthreads();
    }

#pragma unroll
    for (int i = 0; i < 4; i++) {
#pragma unroll
        for (int j = 0; j < 4; j++) {
            int r = bm + ty * 4 + i;
            int c = bn + tx * 4 + j;
            g_feats[(size_t)r * C + c] = acc[i][j] + bias[c];
        }
    }
}

// ---------------- phase 2: src/dst + exp factors + maxdst ----------------
__global__ __launch_bounds__(256) void srcdst_kernel(const float* __restrict__ a)
{
    const int warp = threadIdx.x >> 5;
    const int lane = threadIdx.x & 31;
    const int n = blockIdx.x * 8 + warp;
    if (n >= N_NODES) return;

    const float* f = g_feats + (size_t)n * C;

#pragma unroll
    for (int h = 0; h < NH; h++) {
        float f0 = f[h * 64 + lane];
        float f1 = f[h * 64 + 32 + lane];
        float as0 = a[h * 128 + lane];
        float as1 = a[h * 128 + 32 + lane];
        float ad0 = a[h * 128 + 64 + lane];
        float ad1 = a[h * 128 + 96 + lane];
        float vs = f0 * as0 + f1 * as1;
        float vd = f0 * ad0 + f1 * ad1;
#pragma unroll
        for (int o = 16; o; o >>= 1) {
            vs += __shfl_xor_sync(0xFFFFFFFFu, vs, o);
            vd += __shfl_xor_sync(0xFFFFFFFFu, vd, o);
        }
        if (lane == 0) {
            g_src[n * NH + h] = vs;
            g_DE[n * NH + h] = make_float4(vd, expf(vd), expf(ALPHA * vd), 0.f);
            atomicMax(&g_maxdst_enc[h], fenc(vd));
        }
    }
}

// ---------------- phase 3: masked-softmax attention + PV (fused) ----------------
// grid (NH, N/64); block 256 threads (8 warps), 2 blocks/SM.
// Block tile: 64 i x 64 c (full head) x j chunks of 32.
// Thread (jj=tid&31, wp=tid>>5):
//   prob phase : j = j0+jj, i = wp*8 .. +8     (adj prefetched into regs)
//   PV phase   : i = wp*8 .. +8, c = jj*2,+1   (8 f32x2 accumulators)
// Probs stored transposed as i-quads: s_probQ[i/4][j] (float4) -> broadcast
// LDS.128 reads in PV, conflict-free STS.128 writes in prob phase.
// Software pipeline: chunk c+1's adj/DE/feat global loads are issued right
// after the barrier, before PV(c) -> LDG latency hidden under FFMA2 work.
__global__ __launch_bounds__(256, 2) void attn_kernel(
    const int* __restrict__ adj, float* __restrict__ out)
{
    __shared__ float4 s_probQ[2][16][32];   // [buf][i-quad][j]   16 KB
    __shared__ float  s_feat[2][32][64];    // [buf][j][c]        16 KB
    __shared__ float4 s_SPP[64];            // (src, P1, P2, -)    1 KB
    __shared__ float  s_isum[64];           // 1/denominator

    const int h   = blockIdx.x;
    const int i0  = blockIdx.y * 64;
    const int tid = threadIdx.x;
    const int jj  = tid & 31;
    const int wp  = tid >> 5;

    if (tid < 64) {
        float src = g_src[(i0 + tid) * NH + h];
        float md  = fdec(g_maxdst_enc[h]);
        float bb  = src + md;
        bb = (bb >= 0.f) ? bb : ALPHA * bb;   // b_i = leaky(src + max_dst) >= all logits
        s_SPP[tid] = make_float4(src, expf(src - bb), expf(ALPHA * src - bb), 0.f);
    }
    __syncthreads();

    unsigned long long acc[4][2];
#pragma unroll
    for (int p = 0; p < 4; p++) { acc[p][0] = 0ull; acc[p][1] = 0ull; }
    float psum[8];
#pragma unroll
    for (int k = 0; k < 8; k++) psum[k] = 0.f;

    const float* fbase   = g_feats + h * 64;
    const int*   adjbase = adj + (size_t)(i0 + wp * 8) * N_NODES + jj;

    // feat staging indices: 2 float4 per thread cover [32][64]
    const int fr0 = tid >> 4;
    const int fc0 = (tid & 15) * 4;
    const int fr1 = (tid + 256) >> 4;
    const int fc1 = fc0;

    // ---- prologue: prefetch chunk 0 into registers ----
    int adjreg[8];
#pragma unroll
    for (int k = 0; k < 8; k++) adjreg[k] = adjbase[(size_t)k * N_NODES];
    float4 de = g_DE[jj * NH + h];
    float4 fA = *(const float4*)&fbase[(size_t)fr0 * C + fc0];
    float4 fB = *(const float4*)&fbase[(size_t)fr1 * C + fc1];

    for (int c = 0; c < NC; c++) {
        const int buf = c & 1;

        // ---- stage feats chunk c ----
        *(float4*)&s_feat[buf][fr0][fc0] = fA;
        *(float4*)&s_feat[buf][fr1][fc1] = fB;

        // ---- probs for chunk c from prefetched regs ----
        {
            float pr[8];
#pragma unroll
            for (int k = 0; k < 8; k++) {
                float4 spp = s_SPP[wp * 8 + k];
                float s = spp.x + de.x;
                float p = (adjreg[k] == 1)
                            ? ((s >= 0.f) ? spp.y * de.y : spp.z * de.z)
                            : 0.f;
                pr[k] = p;
                psum[k] += p;
            }
            s_probQ[buf][2 * wp][jj]     = make_float4(pr[0], pr[1], pr[2], pr[3]);
            s_probQ[buf][2 * wp + 1][jj] = make_float4(pr[4], pr[5], pr[6], pr[7]);
        }
        __syncthreads();   // single barrier per chunk

        // ---- prefetch chunk c+1 (overlaps PV below) ----
        if (c + 1 < NC) {
            const int j0n = (c + 1) * 32;
#pragma unroll
            for (int k = 0; k < 8; k++)
                adjreg[k] = adjbase[(size_t)k * N_NODES + j0n];
            de = g_DE[(j0n + jj) * NH + h];
            fA = *(const float4*)&fbase[(size_t)(j0n + fr0) * C + fc0];
            fB = *(const float4*)&fbase[(size_t)(j0n + fr1) * C + fc1];
        }

        // ---- PV chunk c: 8 i x 2 c per thread, packed fp32 FMA ----
#pragma unroll 8
        for (int j = 0; j < 32; j++) {
            float2 fp = *(const float2*)&s_feat[buf][j][jj * 2];
            unsigned long long f0, f1;
            asm("mov.b64 %0, {%1, %1};" : "=l"(f0) : "f"(fp.x));
            asm("mov.b64 %0, {%1, %1};" : "=l"(f1) : "f"(fp.y));
            ulonglong2 pa = *(const ulonglong2*)&s_probQ[buf][2 * wp][j];
            ulonglong2 pb = *(const ulonglong2*)&s_probQ[buf][2 * wp + 1][j];
            asm("fma.rn.f32x2 %0, %1, %2, %0;" : "+l"(acc[0][0]) : "l"(pa.x), "l"(f0));
            asm("fma.rn.f32x2 %0, %1, %2, %0;" : "+l"(acc[0][1]) : "l"(pa.x), "l"(f1));
            asm("fma.rn.f32x2 %0, %1, %2, %0;" : "+l"(acc[1][0]) : "l"(pa.y), "l"(f0));
            asm("fma.rn.f32x2 %0, %1, %2, %0;" : "+l"(acc[1][1]) : "l"(pa.y), "l"(f1));
            asm("fma.rn.f32x2 %0, %1, %2, %0;" : "+l"(acc[2][0]) : "l"(pb.x), "l"(f0));
            asm("fma.rn.f32x2 %0, %1, %2, %0;" : "+l"(acc[2][1]) : "l"(pb.x), "l"(f1));
            asm("fma.rn.f32x2 %0, %1, %2, %0;" : "+l"(acc[3][0]) : "l"(pb.y), "l"(f0));
            asm("fma.rn.f32x2 %0, %1, %2, %0;" : "+l"(acc[3][1]) : "l"(pb.y), "l"(f1));
        }
    }

    // ---- denominators: reduce psum over the 32 jj lanes ----
#pragma unroll
    for (int k = 0; k < 8; k++) {
        float v = psum[k];
#pragma unroll
        for (int o = 16; o; o >>= 1) v += __shfl_xor_sync(0xFFFFFFFFu, v, o);
        if (jj == 0) s_isum[wp * 8 + k] = 1.f / v;
    }
    __syncthreads();

    // ---- write normalized output (float2 stores, coalesced per warp) ----
#pragma unroll
    for (int p = 0; p < 4; p++) {
        int iloc = wp * 8 + 2 * p;
        float r0 = s_isum[iloc];
        float r1 = s_isum[iloc + 1];
        float a0lo, a0hi, a1lo, a1hi;
        asm("mov.b64 {%0, %1}, %2;" : "=f"(a0lo), "=f"(a0hi) : "l"(acc[p][0]));
        asm("mov.b64 {%0, %1}, %2;" : "=f"(a1lo), "=f"(a1hi) : "l"(acc[p][1]));
        float2 v0 = make_float2(a0lo * r0, a1lo * r0);   // row iloc,   cols jj*2, +1
        float2 v1 = make_float2(a0hi * r1, a1hi * r1);   // row iloc+1
        *(float2*)&out[(size_t)(i0 + iloc) * C + h * 64 + jj * 2]     = v0;
        *(float2*)&out[(size_t)(i0 + iloc + 1) * C + h * 64 + jj * 2] = v1;
    }
}

// ---------------- launch ----------------
extern "C" void kernel_launch(void* const* d_in, const int* in_sizes, int n_in,
                              void* d_out, int out_size)
{
    const float* node_feats = (const float*)d_in[0];
    const int*   adj        = (const int*)d_in[1];
    const float* W          = (const float*)d_in[2];
    const float* b          = (const float*)d_in[3];
    const float* a          = (const float*)d_in[4];
    float* out = (float*)d_out;

    init_kernel<<<1, 32>>>();
    gemm_feats<<<dim3(C / 64, N_NODES / 64), 256>>>(node_feats, W, b);
    srcdst_kernel<<<N_NODES / 8, 256>>>(a);
    attn_kernel<<<dim3(NH, N_NODES / 64), 256>>>(adj, out);
}